// round 14
// baseline (speedup 1.0000x reference)
#include <cuda_runtime.h>
#include <math.h>
#include <stdint.h>

#define KC       10
#define BT       256
#define NC       1152
#define ICC      8
#define OC       16
#define BTILE    2
#define NTHREADS 512
#define NWARP    16
#define CSZ      2             // 2-CTA cluster: mild lock-step, exact multicast dedup
#define TILES    9             // 1152 / 128
#define TROWS    128
#define ROWB     576           // padded row stride: rows alternate 64B phases -> conflict-free LDS.128
#define TILE_SMEM (TROWS * ROWB)     // 73728 B
#define TILE_GB  65536         // 128 rows x 512 B
#define SLICE_ROWS (TROWS / CSZ)     // 64 rows per rank
#define DEPTH    3             // triple buffer: 3*73728 = 221184 B dyn smem

struct SmemLayout {
    float sred[NWARP][BTILE][OC];
    float zred[NWARP][BTILE];
    alignas(16) float vsum[BTILE][OC];
};

// ---- PTX helpers ----
__device__ __forceinline__ uint32_t s2u(const void* p) {
    uint32_t a;
    asm("{.reg .u64 t; cvta.to.shared.u64 t, %1; cvt.u32.u64 %0, t;}" : "=r"(a) : "l"(p));
    return a;
}
__device__ __forceinline__ void mbar_init(uint32_t a, uint32_t cnt) {
    asm volatile("mbarrier.init.shared.b64 [%0], %1;" :: "r"(a), "r"(cnt) : "memory");
}
__device__ __forceinline__ void mbar_expect_tx(uint32_t a, uint32_t bytes) {
    asm volatile("mbarrier.arrive.expect_tx.shared.b64 _, [%0], %1;" :: "r"(a), "r"(bytes) : "memory");
}
__device__ __forceinline__ void mbar_wait(uint32_t a, uint32_t phase) {
    asm volatile(
        "{\n\t.reg .pred P;\n\t"
        "WL_%=:\n\t"
        "mbarrier.try_wait.parity.acquire.cta.shared::cta.b64 P, [%0], %1, 0x989680;\n\t"
        "@P bra.uni WD_%=;\n\t"
        "bra.uni WL_%=;\n\t"
        "WD_%=:\n\t}"
        :: "r"(a), "r"(phase) : "memory");
}
__device__ __forceinline__ void mbar_arrive_cluster(uint32_t local_addr, uint32_t peer) {
    asm volatile(
        "{.reg .b32 ra; mapa.shared::cluster.u32 ra, %0, %1;"
        " mbarrier.arrive.shared::cluster.b64 _, [ra];}"
        :: "r"(local_addr), "r"(peer) : "memory");
}
__device__ __forceinline__ void cluster_sync_() {
    asm volatile("barrier.cluster.arrive.aligned;" ::: "memory");
    asm volatile("barrier.cluster.wait.aligned;" ::: "memory");
}
__device__ __forceinline__ void bulk_mc(uint32_t dst, const void* src, uint32_t bytes,
                                        uint32_t mbar, uint16_t mask) {
    asm volatile(
        "cp.async.bulk.shared::cluster.global.mbarrier::complete_tx::bytes.multicast::cluster"
        " [%0], [%1], %2, [%3], %4;"
        :: "r"(dst), "l"(src), "r"(bytes), "r"(mbar), "h"(mask) : "memory");
}

// Warp-0 collective: each lane issues 2 rows of this rank's 64-row slice.
__device__ __forceinline__ void issue_tile(const char* Wk, int tile, uint32_t wb,
                                           uint32_t fullbar, int rank, int lane) {
    const int row0 = rank * SLICE_ROWS + lane * 2;
    const char* src = Wk + (size_t)tile * TILE_GB + (size_t)row0 * 512;
    uint32_t dst = wb + (uint32_t)(tile % DEPTH) * TILE_SMEM + (uint32_t)row0 * ROWB;
    bulk_mc(dst,        src,       512, fullbar, (uint16_t)0x3);
    bulk_mc(dst + ROWB, src + 512, 512, fullbar, (uint16_t)0x3);
}

// ---- reductions (R10-proven) ----
__device__ __forceinline__ float reduce8q(const float a[8], int lane, int* Lp) {
    const bool s1 = lane & 4, s2 = lane & 8, s3 = lane & 16;
    float t4[4], t2[2], r;
    #pragma unroll
    for (int j = 0; j < 4; j++) {
        const float send = s1 ? a[j]     : a[4 + j];
        const float keep = s1 ? a[4 + j] : a[j];
        t4[j] = keep + __shfl_xor_sync(0xffffffffu, send, 4);
    }
    #pragma unroll
    for (int j = 0; j < 2; j++) {
        const float send = s2 ? t4[j]     : t4[2 + j];
        const float keep = s2 ? t4[2 + j] : t4[j];
        t2[j] = keep + __shfl_xor_sync(0xffffffffu, send, 8);
    }
    {
        const float send = s3 ? t2[0] : t2[1];
        const float keep = s3 ? t2[1] : t2[0];
        r = keep + __shfl_xor_sync(0xffffffffu, send, 16);
    }
    *Lp = (s1 ? 4 : 0) | (s2 ? 2 : 0) | (s3 ? 1 : 0);
    return r;
}
__device__ __forceinline__ void store_sred(SmemLayout* sm, int w, int oq, int L, float v) {
    sm->sred[w][L >> 2][4 * oq + (L & 3)] = v;
}
__device__ __forceinline__ void store_zred(SmemLayout* sm, int w, int lane,
                                           float z0, float z1) {
    const float send = (lane & 1) ? z0 : z1;
    const float keep = (lane & 1) ? z1 : z0;
    float zz = keep + __shfl_xor_sync(0xffffffffu, send, 1);
    #pragma unroll
    for (int sft = 2; sft <= 16; sft <<= 1)
        zz += __shfl_xor_sync(0xffffffffu, zz, sft);
    if (lane < 2) sm->zred[w][lane] = 0.25f * zz;   // c replicated over 4 oq-lanes
}
__device__ __forceinline__ void squash_stage(SmemLayout* sm, int t, bool uniform,
                                             bool first, bool writeOut,
                                             float* out, int k, int b0) {
    if (t < 32) {
        const int b = t >> 4, o = t & 15;
        float s = 0.f;
        #pragma unroll
        for (int w = 0; w < NWARP; w++) s += sm->sred[w][b][o];
        float Z;
        if (uniform) {
            Z = (float)NC;
        } else {
            Z = 0.f;
            #pragma unroll
            for (int w = 0; w < NWARP; w++) Z += sm->zred[w][b];
        }
        s /= Z;
        float sq = s * s;
        #pragma unroll
        for (int sft = 1; sft < 16; sft <<= 1)
            sq += __shfl_xor_sync(0xffffffffu, sq, sft);
        const float v = s * sqrtf(sq) / (1.0f + sq);   // squash
        sm->vsum[b][o] = first ? v : (sm->vsum[b][o] + v);
        if (writeOut) out[((size_t)k * BT + b0 + b) * OC + o] = v;
    }
    __syncthreads();
}

__global__ __launch_bounds__(NTHREADS, 1) __cluster_dims__(CSZ, 1, 1)
void caps_routing_kernel(const float* __restrict__ u, const float* __restrict__ W,
                         float* __restrict__ out) {
    extern __shared__ __align__(16) char wbuf[];           // DEPTH x TILE_SMEM
    __shared__ SmemLayout sm;
    __shared__ __align__(8) unsigned long long mbar[2 * DEPTH];  // full[0..2], empty[0..2]

    const int k    = blockIdx.y;
    const int b0   = blockIdx.x * BTILE;
    const int t    = threadIdx.x;
    const int lane = t & 31, w = t >> 5;
    const int oq   = t & 3;              // comps [4oq, 4oq+4)
    const int r    = t >> 2;             // 0..127, local row within each tile

    uint32_t rank;
    asm("mov.u32 %0, %%cluster_ctarank;" : "=r"(rank));
    const uint32_t mb = s2u(mbar);
    const uint32_t wb = s2u(wbuf);
    uint32_t fullA[DEPTH], emptyA[DEPTH];
    #pragma unroll
    for (int i = 0; i < DEPTH; i++) { fullA[i] = mb + 8 * i; emptyA[i] = mb + 8 * (DEPTH + i); }

    if (t == 0) {
        #pragma unroll
        for (int i = 0; i < DEPTH; i++) { mbar_init(fullA[i], 1); mbar_init(emptyA[i], CSZ); }
    }
    __syncthreads();
    cluster_sync_();                     // barriers visible before any multicast

    const char* Wk = (const char*)(W + (size_t)k * NC * ICC * OC);

    // Prologue: warp 0 fills all three buffers (tiles 0..2), 2 copies per lane.
    if (w == 0) {
        #pragma unroll
        for (int pt = 0; pt < DEPTH; pt++) {
            if (lane == 0) mbar_expect_tx(fullA[pt], TILE_GB);
            __syncwarp();
            issue_tile(Wk, pt, wb, fullA[pt], rank, lane);
        }
    }

    // ---- Phase 1: pipelined tiles; u_hat into registers; fuse iter-0 s-sum ----
    float4 uh[BTILE][TILES];
    const float* ub0 = u + (size_t)b0 * NC * ICC;
    const float* ub1 = ub0 + (size_t)NC * ICC;
    float4 s0 = make_float4(0.f,0.f,0.f,0.f), s1 = make_float4(0.f,0.f,0.f,0.f);

    #pragma unroll
    for (int tile = 0; tile < TILES; tile++) {
        const int bsel = tile % DEPTH;
        mbar_wait(fullA[bsel], (tile / DEPTH) & 1);    // acquire: LDS sees TMA data

        const int n = tile * TROWS + r;
        const float4 p0 = *(const float4*)(ub0 + (size_t)n * ICC);
        const float4 p1 = *(const float4*)(ub0 + (size_t)n * ICC + 4);
        const float4 q0 = *(const float4*)(ub1 + (size_t)n * ICC);
        const float4 q1 = *(const float4*)(ub1 + (size_t)n * ICC + 4);
        const float u0[8] = {p0.x, p0.y, p0.z, p0.w, p1.x, p1.y, p1.z, p1.w};
        const float u1[8] = {q0.x, q0.y, q0.z, q0.w, q1.x, q1.y, q1.z, q1.w};

        const char* rowp = wbuf + bsel * TILE_SMEM + r * ROWB + oq * 16;
        float4 a0 = make_float4(0.f,0.f,0.f,0.f);
        float4 a1 = make_float4(0.f,0.f,0.f,0.f);
        #pragma unroll
        for (int i = 0; i < ICC; i++) {
            const float4 wv = *(const float4*)(rowp + i * 64);   // conflict-free (576B stride)
            a0.x = fmaf(wv.x, u0[i], a0.x); a0.y = fmaf(wv.y, u0[i], a0.y);
            a0.z = fmaf(wv.z, u0[i], a0.z); a0.w = fmaf(wv.w, u0[i], a0.w);
            a1.x = fmaf(wv.x, u1[i], a1.x); a1.y = fmaf(wv.y, u1[i], a1.y);
            a1.z = fmaf(wv.z, u1[i], a1.z); a1.w = fmaf(wv.w, u1[i], a1.w);
        }
        uh[0][tile] = a0; uh[1][tile] = a1;
        s0.x += a0.x; s0.y += a0.y; s0.z += a0.z; s0.w += a0.w;
        s1.x += a1.x; s1.y += a1.y; s1.z += a1.z; s1.w += a1.w;

        __syncthreads();                              // all local reads of buf done
        if (w == 0) {                                 // producer work off critical path:
            if (lane == 0) {                          // signal consumed to both CTAs
                mbar_arrive_cluster(emptyA[bsel], 0);
                mbar_arrive_cluster(emptyA[bsel], 1);
            }
            const int tn = tile + DEPTH;
            if (tn < TILES) {                         // refill with tile+3
                mbar_wait(emptyA[bsel], (tile / DEPTH) & 1);  // both CTAs consumed
                if (lane == 0) mbar_expect_tx(fullA[bsel], TILE_GB);
                __syncwarp();
                issue_tile(Wk, tn, wb, fullA[bsel], rank, lane);
            }
        }
    }

    // iter-0 (uniform c) reduction
    {
        const float sa[8] = {s0.x, s0.y, s0.z, s0.w, s1.x, s1.y, s1.z, s1.w};
        int L; const float sv = reduce8q(sa, lane, &L);
        store_sred(&sm, w, oq, L, sv);
    }
    __syncthreads();
    squash_stage(&sm, t, /*uniform=*/true, /*first=*/true, /*writeOut=*/false, out, k, b0);

    // ---- Iterations 1,2: p = uh . vsum (b_ij linear in uh -> no logit storage) ----
    #pragma unroll 1
    for (int iter = 1; iter < 3; iter++) {
        const float4 v0 = *(const float4*)&sm.vsum[0][4 * oq];
        const float4 v1 = *(const float4*)&sm.vsum[1][4 * oq];
        float4 sc0 = make_float4(0.f,0.f,0.f,0.f), sc1 = make_float4(0.f,0.f,0.f,0.f);
        float z0 = 0.f, z1 = 0.f;
        #pragma unroll
        for (int j = 0; j < TILES; j++) {
            const float4 h0 = uh[0][j], h1 = uh[1][j];
            float pa = h0.x * v0.x;
            pa = fmaf(h0.y, v0.y, pa); pa = fmaf(h0.z, v0.z, pa); pa = fmaf(h0.w, v0.w, pa);
            float pb = h1.x * v1.x;
            pb = fmaf(h1.y, v1.y, pb); pb = fmaf(h1.z, v1.z, pb); pb = fmaf(h1.w, v1.w, pb);
            pa += __shfl_xor_sync(0xffffffffu, pa, 1);
            pb += __shfl_xor_sync(0xffffffffu, pb, 1);
            pa += __shfl_xor_sync(0xffffffffu, pa, 2);
            pb += __shfl_xor_sync(0xffffffffu, pb, 2);
            const float c0 = __expf(pa);    // softmax shift-invariant; |p| << 88
            const float c1 = __expf(pb);
            z0 += c0; z1 += c1;
            sc0.x = fmaf(c0, h0.x, sc0.x); sc0.y = fmaf(c0, h0.y, sc0.y);
            sc0.z = fmaf(c0, h0.z, sc0.z); sc0.w = fmaf(c0, h0.w, sc0.w);
            sc1.x = fmaf(c1, h1.x, sc1.x); sc1.y = fmaf(c1, h1.y, sc1.y);
            sc1.z = fmaf(c1, h1.z, sc1.z); sc1.w = fmaf(c1, h1.w, sc1.w);
        }
        const float sa[8] = {sc0.x, sc0.y, sc0.z, sc0.w, sc1.x, sc1.y, sc1.z, sc1.w};
        int L; const float sv = reduce8q(sa, lane, &L);
        store_sred(&sm, w, oq, L, sv);
        store_zred(&sm, w, lane, z0, z1);
        __syncthreads();

        squash_stage(&sm, t, /*uniform=*/false, /*first=*/false,
                     /*writeOut=*/(iter == 2), out, k, b0);
    }

    cluster_sync_();   // no CTA exits while peer multicasts could target its SMEM
}

extern "C" void kernel_launch(void* const* d_in, const int* in_sizes, int n_in,
                              void* d_out, int out_size) {
    const float* u = (const float*)d_in[0];   // [256, 1152, 8]
    const float* W = (const float*)d_in[1];   // [10, 1152, 8, 16]
    float* out = (float*)d_out;               // [10, 256, 1, 1, 16]

    cudaFuncSetAttribute(caps_routing_kernel,
                         cudaFuncAttributeMaxDynamicSharedMemorySize, DEPTH * TILE_SMEM);
    dim3 grid(BT / BTILE, KC);                // 128 x 10; clusters of 2 along x
    caps_routing_kernel<<<grid, NTHREADS, DEPTH * TILE_SMEM>>>(u, W, out);
}

// round 15
// speedup vs baseline: 2.5410x; 2.5410x over previous
#include <cuda_runtime.h>
#include <math.h>

#define KC       10
#define BT       256
#define NC       1152
#define ICC      8
#define OC       16
#define BTILE    2
#define NTHREADS 512          // 16 warps -> 4/SMSP -> 128-reg budget
#define NWARP    16
#define NPAIR    9            // row pairs per thread; keeps 9 rows after merge

struct SmemLayout {
    float sred[NWARP][BTILE][OC];
    float zred[NWARP][BTILE];
    alignas(16) float vsum[BTILE][OC];  // running sum of v's (b_ij = uh . vsum)
};

// Reduce 8 values over the 8 lanes sharing this oq (lane bits 2,3,4).
__device__ __forceinline__ float reduce8q(const float a[8], int lane, int* Lp) {
    const bool s1 = lane & 4, s2 = lane & 8, s3 = lane & 16;
    float t4[4], t2[2], r;
    #pragma unroll
    for (int j = 0; j < 4; j++) {
        const float send = s1 ? a[j]     : a[4 + j];
        const float keep = s1 ? a[4 + j] : a[j];
        t4[j] = keep + __shfl_xor_sync(0xffffffffu, send, 4);
    }
    #pragma unroll
    for (int j = 0; j < 2; j++) {
        const float send = s2 ? t4[j]     : t4[2 + j];
        const float keep = s2 ? t4[2 + j] : t4[j];
        t2[j] = keep + __shfl_xor_sync(0xffffffffu, send, 8);
    }
    {
        const float send = s3 ? t2[0] : t2[1];
        const float keep = s3 ? t2[1] : t2[0];
        r = keep + __shfl_xor_sync(0xffffffffu, send, 16);
    }
    *Lp = (s1 ? 4 : 0) | (s2 ? 2 : 0) | (s3 ? 1 : 0);
    return r;
}

__device__ __forceinline__ void store_sred(SmemLayout* sm, int w, int oq, int L, float v) {
    sm->sred[w][L >> 2][4 * oq + (L & 3)] = v;
}

// c replicated over 4 oq-lanes only -> x0.25 (ip-lanes hold distinct rows).
__device__ __forceinline__ void store_zred(SmemLayout* sm, int w, int lane,
                                           float z0, float z1) {
    const float send = (lane & 1) ? z0 : z1;
    const float keep = (lane & 1) ? z1 : z0;
    float zz = keep + __shfl_xor_sync(0xffffffffu, send, 1);
    #pragma unroll
    for (int sft = 2; sft <= 16; sft <<= 1)
        zz += __shfl_xor_sync(0xffffffffu, zz, sft);
    if (lane < 2) sm->zred[w][lane] = 0.25f * zz;
}

__device__ __forceinline__ void squash_stage(SmemLayout* sm, int t, bool uniform,
                                             bool first, bool writeOut,
                                             float* out, int k, int b0) {
    if (t < 32) {
        const int b = t >> 4, o = t & 15;
        float s = 0.f;
        #pragma unroll
        for (int w = 0; w < NWARP; w++) s += sm->sred[w][b][o];
        float Z;
        if (uniform) {
            Z = (float)NC;
        } else {
            Z = 0.f;
            #pragma unroll
            for (int w = 0; w < NWARP; w++) Z += sm->zred[w][b];
        }
        s /= Z;
        float sq = s * s;
        #pragma unroll
        for (int sft = 1; sft < 16; sft <<= 1)
            sq += __shfl_xor_sync(0xffffffffu, sq, sft);
        const float v = s * sqrtf(sq) / (1.0f + sq);   // squash
        sm->vsum[b][o] = first ? v : (sm->vsum[b][o] + v);
        if (writeOut) out[((size_t)k * BT + b0 + b) * OC + o] = v;
    }
    __syncthreads();
}

// Compute this thread's i-parity partial of u_hat row n (comps [4oq,4oq+4)),
// for both batch elements. Dense W loads: 8 lanes (oq,ip) cover one full line.
__device__ __forceinline__ void row_partial(const float* __restrict__ Wrow,   // + oq*4 + ip*... no: +oq*4
                                            const float* __restrict__ u0row,
                                            const float* __restrict__ u1row,
                                            int ip, float4* A0, float4* A1) {
    const float4 ua0 = *(const float4*)(u0row);
    const float4 ub0 = *(const float4*)(u0row + 4);
    const float4 ua1 = *(const float4*)(u1row);
    const float4 ub1 = *(const float4*)(u1row + 4);
    // i-values for this thread: {ip, 2+ip, 4+ip, 6+ip}
    const float us0[4] = { ip ? ua0.y : ua0.x, ip ? ua0.w : ua0.z,
                           ip ? ub0.y : ub0.x, ip ? ub0.w : ub0.z };
    const float us1[4] = { ip ? ua1.y : ua1.x, ip ? ua1.w : ua1.z,
                           ip ? ub1.y : ub1.x, ip ? ub1.w : ub1.z };
    float4 a0 = make_float4(0.f,0.f,0.f,0.f);
    float4 a1 = make_float4(0.f,0.f,0.f,0.f);
    #pragma unroll
    for (int s = 0; s < 4; s++) {
        // float offset within row: (2s+ip)*16 (+ oq*4 already folded into Wrow)
        const float4 wv = *(const float4*)(Wrow + (2 * s + ip) * OC);
        a0.x = fmaf(wv.x, us0[s], a0.x); a0.y = fmaf(wv.y, us0[s], a0.y);
        a0.z = fmaf(wv.z, us0[s], a0.z); a0.w = fmaf(wv.w, us0[s], a0.w);
        a1.x = fmaf(wv.x, us1[s], a1.x); a1.y = fmaf(wv.y, us1[s], a1.y);
        a1.z = fmaf(wv.z, us1[s], a1.z); a1.w = fmaf(wv.w, us1[s], a1.w);
    }
    *A0 = a0; *A1 = a1;
}

__global__ __launch_bounds__(NTHREADS, 1)
void caps_routing_kernel(const float* __restrict__ u, const float* __restrict__ W,
                         float* __restrict__ out) {
    __shared__ SmemLayout sm;

    const int k    = blockIdx.y;
    const int b0   = blockIdx.x * BTILE;
    const int t    = threadIdx.x;
    const int lane = t & 31, w = t >> 5;
    const int oq   = t & 3;              // comps [4oq, 4oq+4)
    const int ip   = (t >> 2) & 1;       // i-parity: i in {2s+ip}
    const int r    = t >> 3;             // 0..63

    // Register-resident u_hat: thread keeps rows n = r + 128m + 64*ip, m=0..8.
    float4 uh[BTILE][NPAIR];             // 72 regs

    // ---- Phase 1: pair-processed dense loads; merge via one xor-4 exchange ----
    {
        const float* Wk  = W + (size_t)k * NC * ICC * OC + oq * 4;
        const float* ub0 = u + (size_t)b0 * NC * ICC;
        const float* ub1 = ub0 + (size_t)NC * ICC;
        float4 s0 = make_float4(0.f,0.f,0.f,0.f), s1 = make_float4(0.f,0.f,0.f,0.f);
        #pragma unroll
        for (int m = 0; m < NPAIR; m++) {
            const int n0 = r + 128 * m;          // parity-0 row of the pair
            const int n1 = n0 + 64;              // parity-1 row
            float4 P0b0, P0b1, P1b0, P1b1;       // partials: P<row><batch>
            row_partial(Wk + (size_t)n0 * ICC * OC,
                        ub0 + (size_t)n0 * ICC, ub1 + (size_t)n0 * ICC,
                        ip, &P0b0, &P0b1);
            row_partial(Wk + (size_t)n1 * ICC * OC,
                        ub0 + (size_t)n1 * ICC, ub1 + (size_t)n1 * ICC,
                        ip, &P1b0, &P1b1);
            // Keeper: row n_ip. Send the other row's partial; symmetric exchange
            // completes both keepers: send = ip ? P0 : P1, keep = ip ? P1 : P0.
            float4 sb0, sb1, kb0, kb1;
            sb0 = ip ? P0b0 : P1b0;  kb0 = ip ? P1b0 : P0b0;
            sb1 = ip ? P0b1 : P1b1;  kb1 = ip ? P1b1 : P0b1;
            float4 m0, m1;
            m0.x = kb0.x + __shfl_xor_sync(0xffffffffu, sb0.x, 4);
            m0.y = kb0.y + __shfl_xor_sync(0xffffffffu, sb0.y, 4);
            m0.z = kb0.z + __shfl_xor_sync(0xffffffffu, sb0.z, 4);
            m0.w = kb0.w + __shfl_xor_sync(0xffffffffu, sb0.w, 4);
            m1.x = kb1.x + __shfl_xor_sync(0xffffffffu, sb1.x, 4);
            m1.y = kb1.y + __shfl_xor_sync(0xffffffffu, sb1.y, 4);
            m1.z = kb1.z + __shfl_xor_sync(0xffffffffu, sb1.z, 4);
            m1.w = kb1.w + __shfl_xor_sync(0xffffffffu, sb1.w, 4);
            uh[0][m] = m0; uh[1][m] = m1;
            s0.x += m0.x; s0.y += m0.y; s0.z += m0.z; s0.w += m0.w;
            s1.x += m1.x; s1.y += m1.y; s1.z += m1.z; s1.w += m1.w;
        }
        const float sa[8] = {s0.x, s0.y, s0.z, s0.w, s1.x, s1.y, s1.z, s1.w};
        int L; const float sv = reduce8q(sa, lane, &L);
        store_sred(&sm, w, oq, L, sv);
    }
    __syncthreads();

    // ---- Iteration 0: b_ij = 0 => c uniform; s already reduced ----
    squash_stage(&sm, t, /*uniform=*/true, /*first=*/true, /*writeOut=*/false, out, k, b0);

    // ---- Iterations 1,2: p = uh . vsum (b_ij linear in uh -> no logit storage) ----
    #pragma unroll 1
    for (int iter = 1; iter < 3; iter++) {
        const float4 v0 = *(const float4*)&sm.vsum[0][4 * oq];
        const float4 v1 = *(const float4*)&sm.vsum[1][4 * oq];
        float4 sc0 = make_float4(0.f,0.f,0.f,0.f), sc1 = make_float4(0.f,0.f,0.f,0.f);
        float z0 = 0.f, z1 = 0.f;
        #pragma unroll
        for (int j = 0; j < NPAIR; j++) {
            const float4 h0 = uh[0][j], h1 = uh[1][j];
            float pa = h0.x * v0.x;
            pa = fmaf(h0.y, v0.y, pa); pa = fmaf(h0.z, v0.z, pa); pa = fmaf(h0.w, v0.w, pa);
            float pb = h1.x * v1.x;
            pb = fmaf(h1.y, v1.y, pb); pb = fmaf(h1.z, v1.z, pb); pb = fmaf(h1.w, v1.w, pb);
            pa += __shfl_xor_sync(0xffffffffu, pa, 1);   // join 4 quarter-dots (oq lanes)
            pb += __shfl_xor_sync(0xffffffffu, pb, 1);
            pa += __shfl_xor_sync(0xffffffffu, pa, 2);
            pb += __shfl_xor_sync(0xffffffffu, pb, 2);
            const float c0 = __expf(pa);   // softmax shift-invariant; |p| << 88
            const float c1 = __expf(pb);
            z0 += c0; z1 += c1;
            sc0.x = fmaf(c0, h0.x, sc0.x); sc0.y = fmaf(c0, h0.y, sc0.y);
            sc0.z = fmaf(c0, h0.z, sc0.z); sc0.w = fmaf(c0, h0.w, sc0.w);
            sc1.x = fmaf(c1, h1.x, sc1.x); sc1.y = fmaf(c1, h1.y, sc1.y);
            sc1.z = fmaf(c1, h1.z, sc1.z); sc1.w = fmaf(c1, h1.w, sc1.w);
        }
        const float sa[8] = {sc0.x, sc0.y, sc0.z, sc0.w, sc1.x, sc1.y, sc1.z, sc1.w};
        int L; const float sv = reduce8q(sa, lane, &L);
        store_sred(&sm, w, oq, L, sv);
        store_zred(&sm, w, lane, z0, z1);
        __syncthreads();

        squash_stage(&sm, t, /*uniform=*/false, /*first=*/false,
                     /*writeOut=*/(iter == 2), out, k, b0);
    }
}

extern "C" void kernel_launch(void* const* d_in, const int* in_sizes, int n_in,
                              void* d_out, int out_size) {
    const float* u = (const float*)d_in[0];   // [256, 1152, 8]
    const float* W = (const float*)d_in[1];   // [10, 1152, 8, 16]
    float* out = (float*)d_out;               // [10, 256, 1, 1, 16]

    dim3 grid(BT / BTILE, KC);                // 128 x 10 = 1280 CTAs
    caps_routing_kernel<<<grid, NTHREADS>>>(u, W, out);
}